// round 14
// baseline (speedup 1.0000x reference)
#include <cuda_runtime.h>
#include <cuda_fp16.h>
#include <cstdint>

#define B_ 4
#define S_ 2048
#define E_ 1024
#define H_ 16
#define D_ 64
#define BS_ (B_*S_)
#define BHSD (B_*H_*S_*D_)
#define LOG2E 1.4426950408889634f

// Scratch (device globals — no allocations allowed). All fp16.
__device__ __align__(16) __half g_qh[(size_t)BHSD];        // [b,h][s][d], pre-scaled
__device__ __align__(16) __half g_kh[(size_t)BHSD];        // [b,h][s][d]
__device__ __align__(16) __half g_vh[(size_t)BHSD];        // [b,h][s][d]
__device__ __align__(16) __half g_ctxh[(size_t)BS_*E_];    // [s][h*d]
__device__ __align__(16) __half g_xh[(size_t)BS_*E_];      // [s][e]
__device__ __align__(16) __half g_Wqh[H_*E_*D_];           // [h][d][e]
__device__ __align__(16) __half g_Wkh[H_*E_*D_];           // [h][d][e]
__device__ __align__(16) __half g_Wvh[H_*E_*D_];           // [h][d][e]
__device__ __align__(16) __half g_Woh[H_*D_*E_];           // [n][k]

// ---------------------------------------------------------------------------
__device__ __forceinline__ unsigned pack2h(float a, float b) {
    __half2 h = __floats2half2_rn(a, b);
    return *(unsigned*)&h;
}
__device__ __forceinline__ void mma_h(float* c, const unsigned* a, const unsigned* b) {
    asm volatile(
        "mma.sync.aligned.m16n8k16.row.col.f32.f16.f16.f32 "
        "{%0,%1,%2,%3}, {%4,%5,%6,%7}, {%8,%9}, {%0,%1,%2,%3};\n"
        : "+f"(c[0]), "+f"(c[1]), "+f"(c[2]), "+f"(c[3])
        : "r"(a[0]), "r"(a[1]), "r"(a[2]), "r"(a[3]), "r"(b[0]), "r"(b[1]));
}
__device__ __forceinline__ void ldsm4(unsigned* r, uint32_t a) {
    asm volatile("ldmatrix.sync.aligned.m8n8.x4.shared.b16 {%0,%1,%2,%3}, [%4];"
        : "=r"(r[0]), "=r"(r[1]), "=r"(r[2]), "=r"(r[3]) : "r"(a));
}
__device__ __forceinline__ void ldsm4t(unsigned* r, uint32_t a) {
    asm volatile("ldmatrix.sync.aligned.m8n8.x4.trans.shared.b16 {%0,%1,%2,%3}, [%4];"
        : "=r"(r[0]), "=r"(r[1]), "=r"(r[2]), "=r"(r[3]) : "r"(a));
}
__device__ __forceinline__ void cp16(uint32_t d, const __half* s) {
    asm volatile("cp.async.cg.shared.global [%0], [%1], 16;\n" :: "r"(d), "l"(s));
}
__device__ __forceinline__ void cp_commit() { asm volatile("cp.async.commit_group;\n"); }
__device__ __forceinline__ void cp_wait0()  { asm volatile("cp.async.wait_group 0;\n" ::: "memory"); }

// ---------------------------------------------------------------------------
// prep A: x -> fp16 (grid-stride, coalesced float4)
// ---------------------------------------------------------------------------
#define N4_X  (BS_*E_/4)

__global__ void prep_x_kernel(const float4* __restrict__ x)
{
    int i = blockIdx.x * blockDim.x + threadIdx.x;
    int stride = gridDim.x * blockDim.x;
    for (; i < N4_X; i += stride) {
        float4 v = x[i];
        ((uint2*)g_xh)[i] = make_uint2(pack2h(v.x, v.y), pack2h(v.z, v.w));
    }
}

// ---------------------------------------------------------------------------
// prep B: coalesced smem-tiled transpose+convert for Wq/Wk/Wv
// [h][e][d] -> [h][d][e].  grid (D/32=2, E/32=32, 48), block (32,8).
// z encodes wsel*16 + h.
// ---------------------------------------------------------------------------
__global__ void trans_whead_kernel(const float* __restrict__ Wq,
                                   const float* __restrict__ Wk,
                                   const float* __restrict__ Wv)
{
    __shared__ float tile[32][33];
    const int z = blockIdx.z;
    const int wsel = z >> 4, hh = z & 15;
    const float* src = ((wsel == 0) ? Wq : (wsel == 1) ? Wk : Wv) + (size_t)hh * E_ * D_;
    __half* dst = ((wsel == 0) ? g_Wqh : (wsel == 1) ? g_Wkh : g_Wvh) + (size_t)hh * D_ * E_;

    const int c0 = blockIdx.x * 32;   // d block
    const int r0 = blockIdx.y * 32;   // e block
    const int x = threadIdx.x, y = threadIdx.y;

    #pragma unroll
    for (int i = y; i < 32; i += 8)
        tile[i][x] = src[(size_t)(r0 + i) * D_ + c0 + x];
    __syncthreads();
    #pragma unroll
    for (int i = y; i < 32; i += 8)
        dst[(size_t)(c0 + i) * E_ + r0 + x] = __float2half_rn(tile[x][i]);
}

// ---------------------------------------------------------------------------
// prep C: coalesced transpose+convert for Wo: [k][n] -> [n][k].
// grid (32, 32), block (32,8).
// ---------------------------------------------------------------------------
__global__ void trans_wo_kernel(const float* __restrict__ Wo)
{
    __shared__ float tile[32][33];
    const int c0 = blockIdx.x * 32;   // n block
    const int r0 = blockIdx.y * 32;   // k block
    const int x = threadIdx.x, y = threadIdx.y;

    #pragma unroll
    for (int i = y; i < 32; i += 8)
        tile[i][x] = Wo[(size_t)(r0 + i) * E_ + c0 + x];
    __syncthreads();
    #pragma unroll
    for (int i = y; i < 32; i += 8)
        g_Woh[(size_t)(c0 + i) * E_ + r0 + x] = __float2half_rn(tile[x][i]);
}

// ---------------------------------------------------------------------------
// GEMM skeleton (r12 state): CTA tile 128x128, K-tile 64, 2-stage smem ring,
// 128 thr / 4 warps (2x2: warp tile 64x64), fragment double buffering.
// Row stride 72 halves (144B). Stage = 18432 B per operand.
// ---------------------------------------------------------------------------
#define GEMM_SMEM 73728
#define A_STB(s) ((uint32_t)(s) * 18432u)
#define B_STB(s) (36864u + (uint32_t)(s) * 18432u)

struct FragCoord {
    int arow_off, akof, bfsel, bkof, i8;
};

__device__ __forceinline__ void ldfrag(uint32_t aB, uint32_t bB, int ks,
                                       int wm, int wn, const FragCoord& fc,
                                       unsigned a[4][4], unsigned bq[4][4])
{
    #pragma unroll
    for (int mi = 0; mi < 4; mi++) {
        const int row = wm * 64 + mi * 16 + fc.arow_off;
        ldsm4(a[mi], aB + (uint32_t)(row * 144 + (ks * 16 + fc.akof) * 2));
    }
    #pragma unroll
    for (int j = 0; j < 4; j++) {
        const int row = wn * 64 + (2 * j + fc.bfsel) * 8 + fc.i8;
        ldsm4(bq[j], bB + (uint32_t)(row * 144 + (ks * 16 + fc.bkof) * 2));
    }
}

__device__ __forceinline__ void gemm_tile64(float c[4][8][4], uint32_t aB, uint32_t bB,
                                            int wm, int wn, int lane)
{
    FragCoord fc;
    fc.i8       = lane & 7;
    const int sel = lane >> 3;
    fc.arow_off = (sel & 1) * 8 + fc.i8;
    fc.akof     = (sel >> 1) * 8;
    fc.bfsel    = sel >> 1;
    fc.bkof     = (sel & 1) * 8;

    unsigned a[2][4][4], bq[2][4][4];
    ldfrag(aB, bB, 0, wm, wn, fc, a[0], bq[0]);
    #pragma unroll
    for (int ks = 0; ks < 4; ks++) {
        const int cur = ks & 1;
        if (ks < 3) ldfrag(aB, bB, ks + 1, wm, wn, fc, a[cur ^ 1], bq[cur ^ 1]);
        #pragma unroll
        for (int mi = 0; mi < 4; mi++)
            #pragma unroll
            for (int j = 0; j < 4; j++) {
                mma_h(c[mi][2 * j],     a[cur][mi], bq[cur][j]);
                mma_h(c[mi][2 * j + 1], a[cur][mi], bq[cur][j] + 2);
            }
    }
}

// ---------------------------------------------------------------------------
// Kernel 1: fused QKV projection. grid (64, 24), 128 threads, 2 CTA/SM.
// ---------------------------------------------------------------------------
__global__ __launch_bounds__(128, 2) void qkv_kernel(
    const float* __restrict__ bq, const float* __restrict__ bk, const float* __restrict__ bv)
{
    extern __shared__ char smc[];
    const int tid  = threadIdx.x;
    const int m0   = blockIdx.x * 128;
    const int p0   = blockIdx.y * 2;
    const int lane = tid & 31, wid = tid >> 5;
    const int wm   = wid >> 1, wn = wid & 1;
    const int g    = lane >> 2, t = lane & 3;
    const uint32_t smb = (uint32_t)__cvta_generic_to_shared(smc);

    const int r0 = tid >> 3, cpos = tid & 7;
    const uint32_t sOff = (uint32_t)(r0 * 144 + cpos * 16);
    const __half* aBase = g_xh + (size_t)(m0 + r0) * E_ + cpos * 8;
    const int opA = p0 >> 4,        hhA = p0 & 15;
    const int opB = (p0 + 1) >> 4,  hhB = (p0 + 1) & 15;
    const __half* tabA = (opA == 0) ? g_Wqh : (opA == 1) ? g_Wkh : g_Wvh;
    const __half* tabB = (opB == 0) ? g_Wqh : (opB == 1) ? g_Wkh : g_Wvh;
    const __half* bBase0 = tabA + ((size_t)hhA * D_ + r0) * E_ + cpos * 8;
    const __half* bBase1 = tabB + ((size_t)hhB * D_ + r0) * E_ + cpos * 8;

    #pragma unroll
    for (int i = 0; i < 8; i++) {
        cp16(smb + A_STB(0) + sOff + (uint32_t)i * 2304u, aBase + (size_t)i * 16 * E_);
        const __half* bs = (i < 4) ? (bBase0 + (size_t)i * 16 * E_)
                                   : (bBase1 + (size_t)(i - 4) * 16 * E_);
        cp16(smb + B_STB(0) + sOff + (uint32_t)i * 2304u, bs);
    }
    cp_commit();

    float c[4][8][4];
    #pragma unroll
    for (int mi = 0; mi < 4; mi++)
        #pragma unroll
        for (int f = 0; f < 8; f++)
            #pragma unroll
            for (int r = 0; r < 4; r++) c[mi][f][r] = 0.f;

    for (int kt = 0; kt < 16; kt++) {
        cp_wait0();
        __syncthreads();
        if (kt + 1 < 16) {
            const uint32_t s = (uint32_t)((kt + 1) & 1);
            const int kc = (kt + 1) * 64;
            #pragma unroll
            for (int i = 0; i < 8; i++) {
                cp16(smb + A_STB(s) + sOff + (uint32_t)i * 2304u,
                     aBase + (size_t)i * 16 * E_ + kc);
                const __half* bs = (i < 4) ? (bBase0 + (size_t)i * 16 * E_ + kc)
                                           : (bBase1 + (size_t)(i - 4) * 16 * E_ + kc);
                cp16(smb + B_STB(s) + sOff + (uint32_t)i * 2304u, bs);
            }
            cp_commit();
        }
        gemm_tile64(c, smb + A_STB(kt & 1), smb + B_STB(kt & 1), wm, wn, lane);
    }

    const int p  = p0 + wn;
    const int op = p >> 4, hh = p & 15;
    const float* bb = ((op == 0) ? bq : (op == 1) ? bk : bv) + hh * D_;
    __half* outb = (op == 0) ? g_qh : (op == 1) ? g_kh : g_vh;
    const float scl = (op == 0) ? (0.125f * LOG2E) : 1.0f;

    #pragma unroll
    for (int mi = 0; mi < 4; mi++) {
        #pragma unroll
        for (int rr = 0; rr < 2; rr++) {
            const int gr = m0 + wm * 64 + mi * 16 + g + rr * 8;
            const int bbi = gr >> 11, ssi = gr & 2047;
            __half* ob = outb + (((size_t)bbi * H_ + hh) * S_ + ssi) * D_;
            #pragma unroll
            for (int f = 0; f < 8; f++) {
                const int col = f * 8 + t * 2;
                float v0 = (c[mi][f][rr * 2 + 0] + bb[col])     * scl;
                float v1 = (c[mi][f][rr * 2 + 1] + bb[col + 1]) * scl;
                *(unsigned*)(ob + col) = pack2h(v0, v1);
            }
        }
    }
}

// ---------------------------------------------------------------------------
// Kernel 3: output projection. grid (64, 8), 128 threads, 2 CTA/SM.
// ---------------------------------------------------------------------------
__global__ __launch_bounds__(128, 2) void oproj_kernel(
    const float* __restrict__ bo, float* __restrict__ out)
{
    extern __shared__ char smc[];
    const int tid  = threadIdx.x;
    const int m0   = blockIdx.x * 128;
    const int n0   = blockIdx.y * 128;
    const int lane = tid & 31, wid = tid >> 5;
    const int wm   = wid >> 1, wn = wid & 1;
    const int g    = lane >> 2, t = lane & 3;
    const uint32_t smb = (uint32_t)__cvta_generic_to_shared(smc);

    const int r0 = tid >> 3, cpos = tid & 7;
    const uint32_t sOff = (uint32_t)(r0 * 144 + cpos * 16);
    const __half* aBase = g_ctxh + (size_t)(m0 + r0) * E_ + cpos * 8;
    const __half* bBase = g_Woh + (size_t)(n0 + r0) * E_ + cpos * 8;

    #pragma unroll
    for (int i = 0; i < 8; i++) {
        cp16(smb + A_STB(0) + sOff + (uint32_t)i * 2304u, aBase + (size_t)i * 16 * E_);
        cp16(smb + B_STB(0) + sOff + (uint32_t)i * 2304u, bBase + (size_t)i * 16 * E_);
    }
    cp_commit();

    float c[4][8][4];
    #pragma unroll
    for (int mi = 0; mi < 4; mi++)
        #pragma unroll
        for (int f = 0; f < 8; f++)
            #pragma unroll
            for (int r = 0; r < 4; r++) c[mi][f][r] = 0.f;

    for (int kt = 0; kt < 16; kt++) {
        cp_wait0();
        __syncthreads();
        if (kt + 1 < 16) {
            const uint32_t s = (uint32_t)((kt + 1) & 1);
            const int kc = (kt + 1) * 64;
            #pragma unroll
            for (int i = 0; i < 8; i++) {
                cp16(smb + A_STB(s) + sOff + (uint32_t)i * 2304u,
                     aBase + (size_t)i * 16 * E_ + kc);
                cp16(smb + B_STB(s) + sOff + (uint32_t)i * 2304u,
                     bBase + (size_t)i * 16 * E_ + kc);
            }
            cp_commit();
        }
        gemm_tile64(c, smb + A_STB(kt & 1), smb + B_STB(kt & 1), wm, wn, lane);
    }

    #pragma unroll
    for (int mi = 0; mi < 4; mi++) {
        const int row = m0 + wm * 64 + mi * 16 + g;
        #pragma unroll
        for (int f = 0; f < 8; f++) {
            const int col = n0 + wn * 64 + f * 8 + t * 2;
            const float b0v = bo[col], b1v = bo[col + 1];
            float2 v0; v0.x = c[mi][f][0] + b0v; v0.y = c[mi][f][1] + b1v;
            *(float2*)(out + (size_t)row * E_ + col) = v0;
            float2 v1; v1.x = c[mi][f][2] + b0v; v1.y = c[mi][f][3] + b1v;
            *(float2*)(out + (size_t)(row + 8) * E_ + col) = v1;
        }
    }
}

// ---------------------------------------------------------------------------
// Kernel 2: causal flash attention (r12-validated version).
// 128 thr / 4 warps (warp = 32 q-rows), Bq=128, Bkv=64, 2 CTA/SM.
// smem rows 144B: Q[128]@0 | K 2x[64]@18432 | V 2x[64]@36864.
// ---------------------------------------------------------------------------
#define FLASH_SMEM 55296
#define FK_STB(s) (18432u + (uint32_t)(s) * 9216u)
#define FV_STB(s) (36864u + (uint32_t)(s) * 9216u)

__global__ __launch_bounds__(128, 2) void flash_kernel()
{
    extern __shared__ char smc[];
    const uint32_t smb = (uint32_t)__cvta_generic_to_shared(smc);

    const int iq = (int)(gridDim.x - 1 - blockIdx.x);   // heavy-first
    const int h = blockIdx.y, b = blockIdx.z;
    const int q0 = iq * 128;
    const size_t head = ((size_t)b * H_ + h) * S_ * D_;
    const __half* Qg = g_qh + head;
    const __half* Kg = g_kh + head;
    const __half* Vg = g_vh + head;

    const int tid  = threadIdx.x;
    const int lane = tid & 31, wid = tid >> 5;
    const int g    = lane >> 2, t = lane & 3;
    const int i8   = lane & 7, sel = lane >> 3;
    const int bfsel = sel >> 1;
    const int bkof  = (sel & 1) * 8;

    const int r0 = tid >> 3, cpos = tid & 7;
    const uint32_t sOff = (uint32_t)(r0 * 144 + cpos * 16);
    const __half* kBaseG = Kg + (size_t)r0 * D_ + cpos * 8;
    const ptrdiff_t v_delta = Vg - Kg;

    // prologue: Q (8 chunks/thread) + K/V tile 0 (4 chunks/thread each)
    #pragma unroll
    for (int i = 0; i < 8; i++)
        cp16(smb + sOff + (uint32_t)i * 2304u,
             Qg + (size_t)(q0 + r0 + i * 16) * D_ + cpos * 8);
    #pragma unroll
    for (int i = 0; i < 4; i++) {
        cp16(smb + FK_STB(0) + sOff + (uint32_t)i * 2304u, kBaseG + (size_t)i * 16 * D_);
        cp16(smb + FV_STB(0) + sOff + (uint32_t)i * 2304u, kBaseG + v_delta + (size_t)i * 16 * D_);
    }
    cp_commit();
    cp_wait0();
    __syncthreads();

    // Q fragments via ldmatrix (warp-private 32 rows, 2 m16-tiles)
    unsigned aQ[2][4][4];
    {
        const int kof = (sel >> 1) * 8;
        #pragma unroll
        for (int mi = 0; mi < 2; mi++) {
            const int row = wid * 32 + mi * 16 + (sel & 1) * 8 + i8;
            #pragma unroll
            for (int kk = 0; kk < 4; kk++)
                ldsm4(aQ[mi][kk], smb + (uint32_t)(row * 144 + (kk * 16 + kof) * 2));
        }
    }

    float cO[2][8][4];
    #pragma unroll
    for (int mi = 0; mi < 2; mi++)
        #pragma unroll
        for (int f = 0; f < 8; f++)
            #pragma unroll
            for (int r = 0; r < 4; r++) cO[mi][f][r] = 0.f;
    float mS[4] = {-1e30f, -1e30f, -1e30f, -1e30f};
    float lS[4] = {0.f, 0.f, 0.f, 0.f};

    const int jtmax = 2 * iq + 1;
    for (int jt = 0; jt <= jtmax; jt++) {
        if (jt > 0) {
            cp_wait0();
            __syncthreads();
        }
        if (jt < jtmax) {
            const uint32_t st = (uint32_t)((jt + 1) & 1);
            const size_t src = (size_t)(jt + 1) * 4096;
            #pragma unroll
            for (int i = 0; i < 4; i++) {
                cp16(smb + FK_STB(st) + sOff + (uint32_t)i * 2304u,
                     kBaseG + src + (size_t)i * 16 * D_);
                cp16(smb + FV_STB(st) + sOff + (uint32_t)i * 2304u,
                     kBaseG + v_delta + src + (size_t)i * 16 * D_);
            }
            cp_commit();
        }
        const uint32_t kBase = smb + FK_STB(jt & 1);
        const uint32_t vBase = smb + FV_STB(jt & 1);
        const int k0 = jt * 64;

        // S = Q K^T
        float cS[2][8][4];
        #pragma unroll
        for (int mi = 0; mi < 2; mi++)
            #pragma unroll
            for (int f = 0; f < 8; f++)
                #pragma unroll
                for (int r = 0; r < 4; r++) cS[mi][f][r] = 0.f;
        #pragma unroll
        for (int kk = 0; kk < 4; kk++) {
            #pragma unroll
            for (int j = 0; j < 4; j++) {
                unsigned bq[4];
                const int row = (2 * j + bfsel) * 8 + i8;
                ldsm4(bq, kBase + (uint32_t)(row * 144 + (kk * 16 + bkof) * 2));
                #pragma unroll
                for (int mi = 0; mi < 2; mi++) {
                    mma_h(cS[mi][2 * j],     aQ[mi][kk], bq);
                    mma_h(cS[mi][2 * j + 1], aQ[mi][kk], bq + 2);
                }
            }
        }

        // causal mask (diagonal-crossing tiles only)
        if (jt >= 2 * iq) {
            #pragma unroll
            for (int mi = 0; mi < 2; mi++) {
                const int ra = q0 + wid * 32 + mi * 16 + g, rb = ra + 8;
                #pragma unroll
                for (int f = 0; f < 8; f++) {
                    const int col = k0 + f * 8 + t * 2;
                    if (col     > ra) cS[mi][f][0] = -1e30f;
                    if (col + 1 > ra) cS[mi][f][1] = -1e30f;
                    if (col     > rb) cS[mi][f][2] = -1e30f;
                    if (col + 1 > rb) cS[mi][f][3] = -1e30f;
                }
            }
        }

        // online softmax (exp2 domain; Q pre-scaled by 0.125*log2e)
        #pragma unroll
        for (int mi = 0; mi < 2; mi++) {
            float rm0 = -1e30f, rm1 = -1e30f;
            #pragma unroll
            for (int f = 0; f < 8; f++) {
                rm0 = fmaxf(rm0, fmaxf(cS[mi][f][0], cS[mi][f][1]));
                rm1 = fmaxf(rm1, fmaxf(cS[mi][f][2], cS[mi][f][3]));
            }
            rm0 = fmaxf(rm0, __shfl_xor_sync(0xffffffffu, rm0, 1));
            rm0 = fmaxf(rm0, __shfl_xor_sync(0xffffffffu, rm0, 2));
            rm1 = fmaxf(rm1, __shfl_xor_sync(0xffffffffu, rm1, 1));
            rm1 = fmaxf(rm1, __shfl_xor_sync(0xffffffffu, rm1, 2));

            const float nm0 = fmaxf(mS[mi * 2],     rm0);
            const float nm1 = fmaxf(mS[mi * 2 + 1], rm1);
            const float corr0 = exp2f(mS[mi * 2]     - nm0);
            const float corr1 = exp2f(mS[mi * 2 + 1] - nm1);
            mS[mi * 2] = nm0; mS[mi * 2 + 1] = nm1;

            float rs0 = 0.f, rs1 = 0.f;
            #pragma unroll
            for (int f = 0; f < 8; f++) {
                cS[mi][f][0] = exp2f(cS[mi][f][0] - nm0);
                cS[mi][f][1] = exp2f(cS[mi][f][1] - nm0);
                cS[mi][f][2] = exp2f(cS[mi][f][2] - nm1);
                cS[mi][f][3] = exp2f(cS[mi][f][3] - nm1);
                rs0 += cS[mi][f][0] + cS[mi][f][1];
                rs1 += cS[mi][f][2] + cS[mi][f][3];
            }
            rs0 += __shfl_xor_sync(0xffffffffu, rs0, 1);
            rs0 += __shfl_xor_sync(0xffffffffu, rs0, 2);
            rs1 += __shfl_xor_sync(0xffffffffu, rs1, 1);
            rs1 += __shfl_xor_sync(0xffffffffu, rs1, 2);
            lS[mi * 2]     = lS[mi * 2]     * corr0 + rs0;
            lS[mi * 2 + 1] = lS[mi * 2 + 1] * corr1 + rs1;
            #pragma unroll
            for (int f = 0; f < 8; f++) {
                cO[mi][f][0] *= corr0; cO[mi][f][1] *= corr0;
                cO[mi][f][2] *= corr1; cO[mi][f][3] *= corr1;
            }
        }

        // O += P V : P packed from accumulators; V [key][d] via ldmatrix.trans
        #pragma unroll
        for (int kk = 0; kk < 4; kk++) {
            unsigned aP[2][4];
            #pragma unroll
            for (int mi = 0; mi < 2; mi++) {
                aP[mi][0] = pack2h(cS[mi][2 * kk][0],     cS[mi][2 * kk][1]);
                aP[mi][1] = pack2h(cS[mi][2 * kk][2],     cS[mi][2 * kk][3]);
                aP[mi][2] = pack2h(cS[mi][2 * kk + 1][0], cS[mi][2 * kk + 1][1]);
                aP[mi][3] = pack2h(cS[mi][2 * kk + 1][2], cS[mi][2 * kk + 1][3]);
            }
            #pragma unroll
            for (int j = 0; j < 4; j++) {
                unsigned bq[4];
                const int row = kk * 16 + (sel & 1) * 8 + i8;
                const int colb = (2 * j + (sel >> 1)) * 16;
                ldsm4t(bq, vBase + (uint32_t)(row * 144 + colb));
                #pragma unroll
                for (int mi = 0; mi < 2; mi++) {
                    mma_h(cO[mi][2 * j],     aP[mi], bq);
                    mma_h(cO[mi][2 * j + 1], aP[mi], bq + 2);
                }
            }
        }
    }

    // epilogue: normalize, fp16-round, write ctx [s][h*d]
    #pragma unroll
    for (int mi = 0; mi < 2; mi++) {
        const float inv0 = 1.0f / lS[mi * 2];
        const float inv1 = 1.0f / lS[mi * 2 + 1];
        const int q_a = q0 + wid * 32 + mi * 16 + g, q_b = q_a + 8;
        #pragma unroll
        for (int f = 0; f < 8; f++) {
            const int col = h * D_ + f * 8 + t * 2;
            *(unsigned*)(g_ctxh + ((size_t)b * S_ + q_a) * E_ + col) =
                pack2h(cO[mi][f][0] * inv0, cO[mi][f][1] * inv0);
            *(unsigned*)(g_ctxh + ((size_t)b * S_ + q_b) * E_ + col) =
                pack2h(cO[mi][f][2] * inv1, cO[mi][f][3] * inv1);
        }
    }
}

// ---------------------------------------------------------------------------
extern "C" void kernel_launch(void* const* d_in, const int* in_sizes, int n_in,
                              void* d_out, int out_size)
{
    const float* x  = (const float*)d_in[0];
    const float* Wq = (const float*)d_in[1];
    const float* Wk = (const float*)d_in[2];
    const float* Wv = (const float*)d_in[3];
    const float* bq = (const float*)d_in[4];
    const float* bk = (const float*)d_in[5];
    const float* bv = (const float*)d_in[6];
    const float* Wo = (const float*)d_in[7];
    const float* bo = (const float*)d_in[8];
    float* out = (float*)d_out;

    cudaFuncSetAttribute(qkv_kernel,   cudaFuncAttributeMaxDynamicSharedMemorySize, GEMM_SMEM);
    cudaFuncSetAttribute(flash_kernel, cudaFuncAttributeMaxDynamicSharedMemorySize, FLASH_SMEM);
    cudaFuncSetAttribute(oproj_kernel, cudaFuncAttributeMaxDynamicSharedMemorySize, GEMM_SMEM);

    prep_x_kernel<<<2048, 256>>>((const float4*)x);
    trans_whead_kernel<<<dim3(D_ / 32, E_ / 32, 48), dim3(32, 8)>>>(Wq, Wk, Wv);
    trans_wo_kernel<<<dim3(E_ / 32, E_ / 32), dim3(32, 8)>>>(Wo);

    qkv_kernel<<<dim3(BS_ / 128, 24), 128, GEMM_SMEM>>>(bq, bk, bv);
    flash_kernel<<<dim3(S_ / 128, H_, B_), 128, FLASH_SMEM>>>();
    oproj_kernel<<<dim3(BS_ / 128, E_ / 128), 128, GEMM_SMEM>>>(bo, out);
}

// round 15
// speedup vs baseline: 1.5204x; 1.5204x over previous
#include <cuda_runtime.h>
#include <cuda_fp16.h>
#include <cstdint>

#define B_ 4
#define S_ 2048
#define E_ 1024
#define H_ 16
#define D_ 64
#define BS_ (B_*S_)
#define BHSD (B_*H_*S_*D_)
#define LOG2E 1.4426950408889634f

// Scratch (device globals — no allocations allowed). All fp16.
__device__ __align__(16) __half g_qh[(size_t)BHSD];        // [b,h][s][d], pre-scaled
__device__ __align__(16) __half g_kh[(size_t)BHSD];        // [b,h][s][d]
__device__ __align__(16) __half g_vh[(size_t)BHSD];        // [b,h][s][d]
__device__ __align__(16) __half g_ctxh[(size_t)BS_*E_];    // [s][h*d]
__device__ __align__(16) __half g_xh[(size_t)BS_*E_];      // [s][e]
__device__ __align__(16) __half g_Wqh[H_*E_*D_];           // [h][d][e]
__device__ __align__(16) __half g_Wkh[H_*E_*D_];           // [h][d][e]
__device__ __align__(16) __half g_Wvh[H_*E_*D_];           // [h][d][e]
__device__ __align__(16) __half g_Woh[H_*D_*E_];           // [n][k]

// ---------------------------------------------------------------------------
__device__ __forceinline__ unsigned pack2h(float a, float b) {
    __half2 h = __floats2half2_rn(a, b);
    return *(unsigned*)&h;
}
__device__ __forceinline__ void mma_h(float* c, const unsigned* a, const unsigned* b) {
    asm volatile(
        "mma.sync.aligned.m16n8k16.row.col.f32.f16.f16.f32 "
        "{%0,%1,%2,%3}, {%4,%5,%6,%7}, {%8,%9}, {%0,%1,%2,%3};\n"
        : "+f"(c[0]), "+f"(c[1]), "+f"(c[2]), "+f"(c[3])
        : "r"(a[0]), "r"(a[1]), "r"(a[2]), "r"(a[3]), "r"(b[0]), "r"(b[1]));
}
__device__ __forceinline__ void ldsm4(unsigned* r, uint32_t a) {
    asm volatile("ldmatrix.sync.aligned.m8n8.x4.shared.b16 {%0,%1,%2,%3}, [%4];"
        : "=r"(r[0]), "=r"(r[1]), "=r"(r[2]), "=r"(r[3]) : "r"(a));
}
__device__ __forceinline__ void ldsm4t(unsigned* r, uint32_t a) {
    asm volatile("ldmatrix.sync.aligned.m8n8.x4.trans.shared.b16 {%0,%1,%2,%3}, [%4];"
        : "=r"(r[0]), "=r"(r[1]), "=r"(r[2]), "=r"(r[3]) : "r"(a));
}
__device__ __forceinline__ void cp16(uint32_t d, const __half* s) {
    asm volatile("cp.async.cg.shared.global [%0], [%1], 16;\n" :: "r"(d), "l"(s));
}
__device__ __forceinline__ void cp_commit() { asm volatile("cp.async.commit_group;\n"); }
__device__ __forceinline__ void cp_wait0()  { asm volatile("cp.async.wait_group 0;\n" ::: "memory"); }

// ---------------------------------------------------------------------------
// prep: fp16-convert x; transpose+convert Wq/Wk/Wv -> [h][d][e]; Wo -> [n][k]
// ---------------------------------------------------------------------------
#define N4_X  (BS_*E_/4)
#define N4_W  (H_*E_*D_/4)
#define N4_TOT (N4_X + 4*N4_W)

__global__ void prep_kernel(const float* __restrict__ x,
                            const float* __restrict__ Wq, const float* __restrict__ Wk,
                            const float* __restrict__ Wv, const float* __restrict__ Wo)
{
    int i = blockIdx.x * blockDim.x + threadIdx.x;
    int stride = gridDim.x * blockDim.x;
    for (; i < N4_TOT; i += stride) {
        if (i < N4_X) {
            float4 v = ((const float4*)x)[i];
            ((uint2*)g_xh)[i] = make_uint2(pack2h(v.x, v.y), pack2h(v.z, v.w));
        } else if (i < N4_X + 3 * N4_W) {
            int tt = i - N4_X;
            int wsel = tt / N4_W, o4 = tt % N4_W;
            const float* W = (wsel == 0) ? Wq : (wsel == 1) ? Wk : Wv;
            __half* dst = (wsel == 0) ? g_Wqh : (wsel == 1) ? g_Wkh : g_Wvh;
            int o = o4 * 4;
            int e = o & (E_ - 1);
            int rest = o >> 10;
            int d = rest & (D_ - 1);
            int hh = rest >> 6;
            const float* src = W + (size_t)hh * E_ * D_ + d;
            float v0 = src[(size_t)(e + 0) * D_];
            float v1 = src[(size_t)(e + 1) * D_];
            float v2 = src[(size_t)(e + 2) * D_];
            float v3 = src[(size_t)(e + 3) * D_];
            ((uint2*)dst)[o4] = make_uint2(pack2h(v0, v1), pack2h(v2, v3));
        } else {
            int o4 = i - N4_X - 3 * N4_W;
            int o = o4 * 4;
            int k = o & 1023;
            int n = o >> 10;
            float v0 = Wo[(size_t)(k + 0) * E_ + n];
            float v1 = Wo[(size_t)(k + 1) * E_ + n];
            float v2 = Wo[(size_t)(k + 2) * E_ + n];
            float v3 = Wo[(size_t)(k + 3) * E_ + n];
            ((uint2*)g_Woh)[o4] = make_uint2(pack2h(v0, v1), pack2h(v2, v3));
        }
    }
}

// ---------------------------------------------------------------------------
// GEMM skeleton: CTA tile 128x128, K-tile 64, 2-stage smem ring,
// 128 thr / 4 warps (2x2: warp tile 64x64, 128 acc regs/thread),
// fragment double buffering. Row stride 72 halves (144B).
// ---------------------------------------------------------------------------
#define GEMM_SMEM 73728
#define A_STB(s) ((uint32_t)(s) * 18432u)
#define B_STB(s) (36864u + (uint32_t)(s) * 18432u)

struct FragCoord {
    int arow_off, akof, bfsel, bkof, i8;
};

__device__ __forceinline__ void ldfrag(uint32_t aB, uint32_t bB, int ks,
                                       int wm, int wn, const FragCoord& fc,
                                       unsigned a[4][4], unsigned bq[4][4])
{
    #pragma unroll
    for (int mi = 0; mi < 4; mi++) {
        const int row = wm * 64 + mi * 16 + fc.arow_off;
        ldsm4(a[mi], aB + (uint32_t)(row * 144 + (ks * 16 + fc.akof) * 2));
    }
    #pragma unroll
    for (int j = 0; j < 4; j++) {
        const int row = wn * 64 + (2 * j + fc.bfsel) * 8 + fc.i8;
        ldsm4(bq[j], bB + (uint32_t)(row * 144 + (ks * 16 + fc.bkof) * 2));
    }
}

__device__ __forceinline__ void gemm_tile64(float c[4][8][4], uint32_t aB, uint32_t bB,
                                            int wm, int wn, int lane)
{
    FragCoord fc;
    fc.i8       = lane & 7;
    const int sel = lane >> 3;
    fc.arow_off = (sel & 1) * 8 + fc.i8;
    fc.akof     = (sel >> 1) * 8;
    fc.bfsel    = sel >> 1;
    fc.bkof     = (sel & 1) * 8;

    unsigned a[2][4][4], bq[2][4][4];
    ldfrag(aB, bB, 0, wm, wn, fc, a[0], bq[0]);
    #pragma unroll
    for (int ks = 0; ks < 4; ks++) {
        const int cur = ks & 1;
        if (ks < 3) ldfrag(aB, bB, ks + 1, wm, wn, fc, a[cur ^ 1], bq[cur ^ 1]);
        #pragma unroll
        for (int mi = 0; mi < 4; mi++)
            #pragma unroll
            for (int j = 0; j < 4; j++) {
                mma_h(c[mi][2 * j],     a[cur][mi], bq[cur][j]);
                mma_h(c[mi][2 * j + 1], a[cur][mi], bq[cur][j] + 2);
            }
    }
}

// ---------------------------------------------------------------------------
// Kernel 1: fused QKV projection. grid (64, 24), 128 threads, 2 CTA/SM.
// ---------------------------------------------------------------------------
__global__ __launch_bounds__(128, 2) void qkv_kernel(
    const float* __restrict__ bq, const float* __restrict__ bk, const float* __restrict__ bv)
{
    extern __shared__ char smc[];
    const int tid  = threadIdx.x;
    const int m0   = blockIdx.x * 128;
    const int p0   = blockIdx.y * 2;
    const int lane = tid & 31, wid = tid >> 5;
    const int wm   = wid >> 1, wn = wid & 1;
    const int g    = lane >> 2, t = lane & 3;
    const uint32_t smb = (uint32_t)__cvta_generic_to_shared(smc);

    const int r0 = tid >> 3, cpos = tid & 7;
    const uint32_t sOff = (uint32_t)(r0 * 144 + cpos * 16);
    const __half* aBase = g_xh + (size_t)(m0 + r0) * E_ + cpos * 8;
    const int opA = p0 >> 4,        hhA = p0 & 15;
    const int opB = (p0 + 1) >> 4,  hhB = (p0 + 1) & 15;
    const __half* tabA = (opA == 0) ? g_Wqh : (opA == 1) ? g_Wkh : g_Wvh;
    const __half* tabB = (opB == 0) ? g_Wqh : (opB == 1) ? g_Wkh : g_Wvh;
    const __half* bBase0 = tabA + ((size_t)hhA * D_ + r0) * E_ + cpos * 8;
    const __half* bBase1 = tabB + ((size_t)hhB * D_ + r0) * E_ + cpos * 8;

    #pragma unroll
    for (int i = 0; i < 8; i++) {
        cp16(smb + A_STB(0) + sOff + (uint32_t)i * 2304u, aBase + (size_t)i * 16 * E_);
        const __half* bs = (i < 4) ? (bBase0 + (size_t)i * 16 * E_)
                                   : (bBase1 + (size_t)(i - 4) * 16 * E_);
        cp16(smb + B_STB(0) + sOff + (uint32_t)i * 2304u, bs);
    }
    cp_commit();

    float c[4][8][4];
    #pragma unroll
    for (int mi = 0; mi < 4; mi++)
        #pragma unroll
        for (int f = 0; f < 8; f++)
            #pragma unroll
            for (int r = 0; r < 4; r++) c[mi][f][r] = 0.f;

    for (int kt = 0; kt < 16; kt++) {
        cp_wait0();
        __syncthreads();
        if (kt + 1 < 16) {
            const uint32_t s = (uint32_t)((kt + 1) & 1);
            const int kc = (kt + 1) * 64;
            #pragma unroll
            for (int i = 0; i < 8; i++) {
                cp16(smb + A_STB(s) + sOff + (uint32_t)i * 2304u,
                     aBase + (size_t)i * 16 * E_ + kc);
                const __half* bs = (i < 4) ? (bBase0 + (size_t)i * 16 * E_ + kc)
                                           : (bBase1 + (size_t)(i - 4) * 16 * E_ + kc);
                cp16(smb + B_STB(s) + sOff + (uint32_t)i * 2304u, bs);
            }
            cp_commit();
        }
        gemm_tile64(c, smb + A_STB(kt & 1), smb + B_STB(kt & 1), wm, wn, lane);
    }

    const int p  = p0 + wn;
    const int op = p >> 4, hh = p & 15;
    const float* bb = ((op == 0) ? bq : (op == 1) ? bk : bv) + hh * D_;
    __half* outb = (op == 0) ? g_qh : (op == 1) ? g_kh : g_vh;
    const float scl = (op == 0) ? (0.125f * LOG2E) : 1.0f;

    #pragma unroll
    for (int mi = 0; mi < 4; mi++) {
        #pragma unroll
        for (int rr = 0; rr < 2; rr++) {
            const int gr = m0 + wm * 64 + mi * 16 + g + rr * 8;
            const int bbi = gr >> 11, ssi = gr & 2047;
            __half* ob = outb + (((size_t)bbi * H_ + hh) * S_ + ssi) * D_;
            #pragma unroll
            for (int f = 0; f < 8; f++) {
                const int col = f * 8 + t * 2;
                float v0 = (c[mi][f][rr * 2 + 0] + bb[col])     * scl;
                float v1 = (c[mi][f][rr * 2 + 1] + bb[col + 1]) * scl;
                *(unsigned*)(ob + col) = pack2h(v0, v1);
            }
        }
    }
}

// ---------------------------------------------------------------------------
// Kernel 3: output projection. grid (64, 8), 128 threads, 2 CTA/SM.
// ---------------------------------------------------------------------------
__global__ __launch_bounds__(128, 2) void oproj_kernel(
    const float* __restrict__ bo, float* __restrict__ out)
{
    extern __shared__ char smc[];
    const int tid  = threadIdx.x;
    const int m0   = blockIdx.x * 128;
    const int n0   = blockIdx.y * 128;
    const int lane = tid & 31, wid = tid >> 5;
    const int wm   = wid >> 1, wn = wid & 1;
    const int g    = lane >> 2, t = lane & 3;
    const uint32_t smb = (uint32_t)__cvta_generic_to_shared(smc);

    const int r0 = tid >> 3, cpos = tid & 7;
    const uint32_t sOff = (uint32_t)(r0 * 144 + cpos * 16);
    const __half* aBase = g_ctxh + (size_t)(m0 + r0) * E_ + cpos * 8;
    const __half* bBase = g_Woh + (size_t)(n0 + r0) * E_ + cpos * 8;

    #pragma unroll
    for (int i = 0; i < 8; i++) {
        cp16(smb + A_STB(0) + sOff + (uint32_t)i * 2304u, aBase + (size_t)i * 16 * E_);
        cp16(smb + B_STB(0) + sOff + (uint32_t)i * 2304u, bBase + (size_t)i * 16 * E_);
    }
    cp_commit();

    float c[4][8][4];
    #pragma unroll
    for (int mi = 0; mi < 4; mi++)
        #pragma unroll
        for (int f = 0; f < 8; f++)
            #pragma unroll
            for (int r = 0; r < 4; r++) c[mi][f][r] = 0.f;

    for (int kt = 0; kt < 16; kt++) {
        cp_wait0();
        __syncthreads();
        if (kt + 1 < 16) {
            const uint32_t s = (uint32_t)((kt + 1) & 1);
            const int kc = (kt + 1) * 64;
            #pragma unroll
            for (int i = 0; i < 8; i++) {
                cp16(smb + A_STB(s) + sOff + (uint32_t)i * 2304u,
                     aBase + (size_t)i * 16 * E_ + kc);
                cp16(smb + B_STB(s) + sOff + (uint32_t)i * 2304u,
                     bBase + (size_t)i * 16 * E_ + kc);
            }
            cp_commit();
        }
        gemm_tile64(c, smb + A_STB(kt & 1), smb + B_STB(kt & 1), wm, wn, lane);
    }

    #pragma unroll
    for (int mi = 0; mi < 4; mi++) {
        const int row = m0 + wm * 64 + mi * 16 + g;
        #pragma unroll
        for (int f = 0; f < 8; f++) {
            const int col = n0 + wn * 64 + f * 8 + t * 2;
            const float b0v = bo[col], b1v = bo[col + 1];
            float2 v0; v0.x = c[mi][f][0] + b0v; v0.y = c[mi][f][1] + b1v;
            *(float2*)(out + (size_t)row * E_ + col) = v0;
            float2 v1; v1.x = c[mi][f][2] + b0v; v1.y = c[mi][f][3] + b1v;
            *(float2*)(out + (size_t)(row + 8) * E_ + col) = v1;
        }
    }
}

// ---------------------------------------------------------------------------
// Kernel 2: causal flash attention (r12-validated version).
// 128 thr / 4 warps (warp = 32 q-rows), Bq=128, Bkv=64, 2 CTA/SM.
// smem rows 144B: Q[128]@0 | K 2x[64]@18432 | V 2x[64]@36864.
// ---------------------------------------------------------------------------
#define FLASH_SMEM 55296
#define FK_STB(s) (18432u + (uint32_t)(s) * 9216u)
#define FV_STB(s) (36864u + (uint32_t)(s) * 9216u)

__global__ __launch_bounds__(128, 2) void flash_kernel()
{
    extern __shared__ char smc[];
    const uint32_t smb = (uint32_t)__cvta_generic_to_shared(smc);

    const int iq = (int)(gridDim.x - 1 - blockIdx.x);   // heavy-first
    const int h = blockIdx.y, b = blockIdx.z;
    const int q0 = iq * 128;
    const size_t head = ((size_t)b * H_ + h) * S_ * D_;
    const __half* Qg = g_qh + head;
    const __half* Kg = g_kh + head;
    const __half* Vg = g_vh + head;

    const int tid  = threadIdx.x;
    const int lane = tid & 31, wid = tid >> 5;
    const int g    = lane >> 2, t = lane & 3;
    const int i8   = lane & 7, sel = lane >> 3;
    const int bfsel = sel >> 1;
    const int bkof  = (sel & 1) * 8;

    const int r0 = tid >> 3, cpos = tid & 7;
    const uint32_t sOff = (uint32_t)(r0 * 144 + cpos * 16);
    const __half* kBaseG = Kg + (size_t)r0 * D_ + cpos * 8;
    const ptrdiff_t v_delta = Vg - Kg;

    // prologue: Q (8 chunks/thread) + K/V tile 0 (4 chunks/thread each)
    #pragma unroll
    for (int i = 0; i < 8; i++)
        cp16(smb + sOff + (uint32_t)i * 2304u,
             Qg + (size_t)(q0 + r0 + i * 16) * D_ + cpos * 8);
    #pragma unroll
    for (int i = 0; i < 4; i++) {
        cp16(smb + FK_STB(0) + sOff + (uint32_t)i * 2304u, kBaseG + (size_t)i * 16 * D_);
        cp16(smb + FV_STB(0) + sOff + (uint32_t)i * 2304u, kBaseG + v_delta + (size_t)i * 16 * D_);
    }
    cp_commit();
    cp_wait0();
    __syncthreads();

    // Q fragments via ldmatrix (warp-private 32 rows, 2 m16-tiles)
    unsigned aQ[2][4][4];
    {
        const int kof = (sel >> 1) * 8;
        #pragma unroll
        for (int mi = 0; mi < 2; mi++) {
            const int row = wid * 32 + mi * 16 + (sel & 1) * 8 + i8;
            #pragma unroll
            for (int kk = 0; kk < 4; kk++)
                ldsm4(aQ[mi][kk], smb + (uint32_t)(row * 144 + (kk * 16 + kof) * 2));
        }
    }

    float cO[2][8][4];
    #pragma unroll
    for (int mi = 0; mi < 2; mi++)
        #pragma unroll
        for (int f = 0; f < 8; f++)
            #pragma unroll
            for (int r = 0; r < 4; r++) cO[mi][f][r] = 0.f;
    float mS[4] = {-1e30f, -1e30f, -1e30f, -1e30f};
    float lS[4] = {0.f, 0.f, 0.f, 0.f};

    const int jtmax = 2 * iq + 1;
    for (int jt = 0; jt <= jtmax; jt++) {
        if (jt > 0) {
            cp_wait0();
            __syncthreads();
        }
        if (jt < jtmax) {
            const uint32_t st = (uint32_t)((jt + 1) & 1);
            const size_t src = (size_t)(jt + 1) * 4096;
            #pragma unroll
            for (int i = 0; i < 4; i++) {
                cp16(smb + FK_STB(st) + sOff + (uint32_t)i * 2304u,
                     kBaseG + src + (size_t)i * 16 * D_);
                cp16(smb + FV_STB(st) + sOff + (uint32_t)i * 2304u,
                     kBaseG + v_delta + src + (size_t)i * 16 * D_);
            }
            cp_commit();
        }
        const uint32_t kBase = smb + FK_STB(jt & 1);
        const uint32_t vBase = smb + FV_STB(jt & 1);
        const int k0 = jt * 64;

        // S = Q K^T
        float cS[2][8][4];
        #pragma unroll
        for (int mi = 0; mi < 2; mi++)
            #pragma unroll
            for (int f = 0; f < 8; f++)
                #pragma unroll
                for (int r = 0; r < 4; r++) cS[mi][f][r] = 0.f;
        #pragma unroll
        for (int kk = 0; kk < 4; kk++) {
            #pragma unroll
            for (int j = 0; j < 4; j++) {
                unsigned bq[4];
                const int row = (2 * j + bfsel) * 8 + i8;
                ldsm4(bq, kBase + (uint32_t)(row * 144 + (kk * 16 + bkof) * 2));
                #pragma unroll
                for (int mi = 0; mi < 2; mi++) {
                    mma_h(cS[mi][2 * j],     aQ[mi][kk], bq);
                    mma_h(cS[mi][2 * j + 1], aQ[mi][kk], bq + 2);
                }
            }
        }

        // causal mask (diagonal-crossing tiles only)
        if (jt >= 2 * iq) {
            #pragma unroll
            for (int mi = 0; mi < 2; mi++) {
                const int ra = q0 + wid * 32 + mi * 16 + g, rb = ra + 8;
                #pragma unroll
                for (int f = 0; f < 8; f++) {
                    const int col = k0 + f * 8 + t * 2;
                    if (col     > ra) cS[mi][f][0] = -1e30f;
                    if (col + 1 > ra) cS[mi][f][1] = -1e30f;
                    if (col     > rb) cS[mi][f][2] = -1e30f;
                    if (col + 1 > rb) cS[mi][f][3] = -1e30f;
                }
            }
        }

        // online softmax (exp2 domain; Q pre-scaled by 0.125*log2e)
        #pragma unroll
        for (int mi = 0; mi < 2; mi++) {
            float rm0 = -1e30f, rm1 = -1e30f;
            #pragma unroll
            for (int f = 0; f < 8; f++) {
                rm0 = fmaxf(rm0, fmaxf(cS[mi][f][0], cS[mi][f][1]));
                rm1 = fmaxf(rm1, fmaxf(cS[mi][f][2], cS[mi][f][3]));
            }
            rm0 = fmaxf(rm0, __shfl_xor_sync(0xffffffffu, rm0, 1));
            rm0 = fmaxf(rm0, __shfl_xor_sync(0xffffffffu, rm0, 2));
            rm1 = fmaxf(rm1, __shfl_xor_sync(0xffffffffu, rm1, 1));
            rm1 = fmaxf(rm1, __shfl_xor_sync(0xffffffffu, rm1, 2));

            const float nm0 = fmaxf(mS[mi * 2],     rm0);
            const float nm1 = fmaxf(mS[mi * 2 + 1], rm1);
            const float corr0 = exp2f(mS[mi * 2]     - nm0);
            const float corr1 = exp2f(mS[mi * 2 + 1] - nm1);
            mS[mi * 2] = nm0; mS[mi * 2 + 1] = nm1;

            float rs0 = 0.f, rs1 = 0.f;
            #pragma unroll
            for (int f = 0; f < 8; f++) {
                cS[mi][f][0] = exp2f(cS[mi][f][0] - nm0);
                cS[mi][f][1] = exp2f(cS[mi][f][1] - nm0);
                cS[mi][f][2] = exp2f(cS[mi][f][2] - nm1);
                cS[mi][f][3] = exp2f(cS[mi][f][3] - nm1);
                rs0 += cS[mi][f][0] + cS[mi][f][1];
                rs1 += cS[mi][f][2] + cS[mi][f][3];
            }
            rs0 += __shfl_xor_sync(0xffffffffu, rs0, 1);
            rs0 += __shfl_xor_sync(0xffffffffu, rs0, 2);
            rs1 += __shfl_xor_sync(0xffffffffu, rs1, 1);
            rs1 += __shfl_xor_sync(0xffffffffu, rs1, 2);
            lS[mi * 2]     = lS[mi * 2]     * corr0 + rs0;
            lS[mi * 2 + 1] = lS[mi * 2 + 1] * corr1 + rs1;
            #pragma unroll
            for (int f = 0; f < 8; f++) {
                cO[mi][f][0] *= corr0; cO[mi][f][1] *= corr0;
                cO[mi][f][2] *= corr1; cO[mi][f][3] *= corr1;
            }
        }

        // O += P V : P packed from accumulators; V [key][d] via ldmatrix.trans
        #pragma unroll
        for (int kk = 0; kk < 4; kk++) {
            unsigned aP[2][4];
            #pragma unroll
            for (int mi = 0; mi < 2; mi++) {
                aP[mi][0] = pack2h(cS[mi][2 * kk][0],     cS[mi][2 * kk][1]);
                aP[mi][1] = pack2h(cS[mi][2 * kk][2],     cS[mi][2 * kk][3]);
                aP[mi][2] = pack2h(cS[mi][2 * kk + 1][0], cS[mi][2 * kk + 1][1]);
                aP[mi][3] = pack2h(cS[mi][2 * kk + 1][2], cS[mi][2 * kk + 1][3]);
            }
            #pragma unroll
            for (int j = 0; j < 4; j++) {
                unsigned bq[4];
                const int row = kk * 16 + (sel & 1) * 8 + i8;
                const int colb = (2 * j + (sel >> 1)) * 16;
                ldsm4t(bq, vBase + (uint32_t)(row * 144 + colb));
                #pragma unroll
                for (int mi = 0; mi < 2; mi++) {
                    mma_h(cO[mi][2 * j],     aP[mi], bq);
                    mma_h(cO[mi][2 * j + 1], aP[mi], bq + 2);
                }
            }
        }
    }

    // epilogue: normalize, fp16-round, write ctx [s][h*d]
    #pragma unroll
    for (int mi = 0; mi < 2; mi++) {
        const float inv0 = 1.0f / lS[mi * 2];
        const float inv1 = 1.0f / lS[mi * 2 + 1];
        const int q_a = q0 + wid * 32 + mi * 16 + g, q_b = q_a + 8;
        #pragma unroll
        for (int f = 0; f < 8; f++) {
            const int col = h * D_ + f * 8 + t * 2;
            *(unsigned*)(g_ctxh + ((size_t)b * S_ + q_a) * E_ + col) =
                pack2h(cO[mi][f][0] * inv0, cO[mi][f][1] * inv0);
            *(unsigned*)(g_ctxh + ((size_t)b * S_ + q_b) * E_ + col) =
                pack2h(cO[mi][f][2] * inv1, cO[mi][f][3] * inv1);
        }
    }
}

// ---------------------------------------------------------------------------
extern "C" void kernel_launch(void* const* d_in, const int* in_sizes, int n_in,
                              void* d_out, int out_size)
{
    const float* x  = (const float*)d_in[0];
    const float* Wq = (const float*)d_in[1];
    const float* Wk = (const float*)d_in[2];
    const float* Wv = (const float*)d_in[3];
    const float* bq = (const float*)d_in[4];
    const float* bk = (const float*)d_in[5];
    const float* bv = (const float*)d_in[6];
    const float* Wo = (const float*)d_in[7];
    const float* bo = (const float*)d_in[8];
    float* out = (float*)d_out;

    cudaFuncSetAttribute(qkv_kernel,   cudaFuncAttributeMaxDynamicSharedMemorySize, GEMM_SMEM);
    cudaFuncSetAttribute(flash_kernel, cudaFuncAttributeMaxDynamicSharedMemorySize, FLASH_SMEM);
    cudaFuncSetAttribute(oproj_kernel, cudaFuncAttributeMaxDynamicSharedMemorySize, GEMM_SMEM);

    prep_kernel<<<2368, 256>>>(x, Wq, Wk, Wv, Wo);
    qkv_kernel<<<dim3(BS_ / 128, 24), 128, GEMM_SMEM>>>(bq, bk, bv);
    flash_kernel<<<dim3(S_ / 128, H_, B_), 128, FLASH_SMEM>>>();
    oproj_kernel<<<dim3(BS_ / 128, E_ / 128), 128, GEMM_SMEM>>>(bo, out);
}

// round 16
// speedup vs baseline: 1.5622x; 1.0275x over previous
#include <cuda_runtime.h>
#include <cuda_fp16.h>
#include <cstdint>

#define B_ 4
#define S_ 2048
#define E_ 1024
#define H_ 16
#define D_ 64
#define BS_ (B_*S_)
#define BHSD (B_*H_*S_*D_)
#define LOG2E 1.4426950408889634f

// Scratch (device globals — no allocations allowed). All fp16.
__device__ __align__(16) __half g_qh[(size_t)BHSD];        // [b,h][s][d], pre-scaled
__device__ __align__(16) __half g_kh[(size_t)BHSD];        // [b,h][s][d]
__device__ __align__(16) __half g_vh[(size_t)BHSD];        // [b,h][s][d]
__device__ __align__(16) __half g_ctxh[(size_t)BS_*E_];    // [s][h*d]
__device__ __align__(16) __half g_xh[(size_t)BS_*E_];      // [s][e]
__device__ __align__(16) __half g_Wqh[H_*E_*D_];           // [h][d][e]
__device__ __align__(16) __half g_Wkh[H_*E_*D_];           // [h][d][e]
__device__ __align__(16) __half g_Wvh[H_*E_*D_];           // [h][d][e]
__device__ __align__(16) __half g_Woh[H_*D_*E_];           // [n][k]

// ---------------------------------------------------------------------------
__device__ __forceinline__ unsigned pack2h(float a, float b) {
    __half2 h = __floats2half2_rn(a, b);
    return *(unsigned*)&h;
}
__device__ __forceinline__ void mma_h(float* c, const unsigned* a, const unsigned* b) {
    asm volatile(
        "mma.sync.aligned.m16n8k16.row.col.f32.f16.f16.f32 "
        "{%0,%1,%2,%3}, {%4,%5,%6,%7}, {%8,%9}, {%0,%1,%2,%3};\n"
        : "+f"(c[0]), "+f"(c[1]), "+f"(c[2]), "+f"(c[3])
        : "r"(a[0]), "r"(a[1]), "r"(a[2]), "r"(a[3]), "r"(b[0]), "r"(b[1]));
}
__device__ __forceinline__ void ldsm4(unsigned* r, uint32_t a) {
    asm volatile("ldmatrix.sync.aligned.m8n8.x4.shared.b16 {%0,%1,%2,%3}, [%4];"
        : "=r"(r[0]), "=r"(r[1]), "=r"(r[2]), "=r"(r[3]) : "r"(a));
}
__device__ __forceinline__ void ldsm4t(unsigned* r, uint32_t a) {
    asm volatile("ldmatrix.sync.aligned.m8n8.x4.trans.shared.b16 {%0,%1,%2,%3}, [%4];"
        : "=r"(r[0]), "=r"(r[1]), "=r"(r[2]), "=r"(r[3]) : "r"(a));
}
__device__ __forceinline__ void cp16(uint32_t d, const __half* s) {
    asm volatile("cp.async.cg.shared.global [%0], [%1], 16;\n" :: "r"(d), "l"(s));
}
__device__ __forceinline__ void cp_commit() { asm volatile("cp.async.commit_group;\n"); }
__device__ __forceinline__ void cp_wait0()  { asm volatile("cp.async.wait_group 0;\n" ::: "memory"); }

// ---------------------------------------------------------------------------
// prep: fp16-convert x; transpose+convert Wq/Wk/Wv -> [h][d][e]; Wo -> [n][k]
// (r12-validated fused single launch)
// ---------------------------------------------------------------------------
#define N4_X  (BS_*E_/4)
#define N4_W  (H_*E_*D_/4)
#define N4_TOT (N4_X + 4*N4_W)

__global__ void prep_kernel(const float* __restrict__ x,
                            const float* __restrict__ Wq, const float* __restrict__ Wk,
                            const float* __restrict__ Wv, const float* __restrict__ Wo)
{
    int i = blockIdx.x * blockDim.x + threadIdx.x;
    int stride = gridDim.x * blockDim.x;
    for (; i < N4_TOT; i += stride) {
        if (i < N4_X) {
            float4 v = ((const float4*)x)[i];
            ((uint2*)g_xh)[i] = make_uint2(pack2h(v.x, v.y), pack2h(v.z, v.w));
        } else if (i < N4_X + 3 * N4_W) {
            int tt = i - N4_X;
            int wsel = tt / N4_W, o4 = tt % N4_W;
            const float* W = (wsel == 0) ? Wq : (wsel == 1) ? Wk : Wv;
            __half* dst = (wsel == 0) ? g_Wqh : (wsel == 1) ? g_Wkh : g_Wvh;
            int o = o4 * 4;
            int e = o & (E_ - 1);
            int rest = o >> 10;
            int d = rest & (D_ - 1);
            int hh = rest >> 6;
            const float* src = W + (size_t)hh * E_ * D_ + d;
            float v0 = src[(size_t)(e + 0) * D_];
            float v1 = src[(size_t)(e + 1) * D_];
            float v2 = src[(size_t)(e + 2) * D_];
            float v3 = src[(size_t)(e + 3) * D_];
            ((uint2*)dst)[o4] = make_uint2(pack2h(v0, v1), pack2h(v2, v3));
        } else {
            int o4 = i - N4_X - 3 * N4_W;
            int o = o4 * 4;
            int k = o & 1023;
            int n = o >> 10;
            float v0 = Wo[(size_t)(k + 0) * E_ + n];
            float v1 = Wo[(size_t)(k + 1) * E_ + n];
            float v2 = Wo[(size_t)(k + 2) * E_ + n];
            float v3 = Wo[(size_t)(k + 3) * E_ + n];
            ((uint2*)g_Woh)[o4] = make_uint2(pack2h(v0, v1), pack2h(v2, v3));
        }
    }
}

// ---------------------------------------------------------------------------
// GEMM skeleton (r9-validated, best measured oproj): CTA tile 128x128,
// K-tile 64, 2-stage ring, 256 thr / 8 warps (wm 0..3 x wn 0..1, warp 32x64).
// Row stride 72 halves (144B). Stage = 18432 B per operand.
// ---------------------------------------------------------------------------
#define GEMM_SMEM 73728
#define A_STB(s) ((uint32_t)(s) * 18432u)
#define B_STB(s) (36864u + (uint32_t)(s) * 18432u)

__device__ __forceinline__ void gemm_tile64(float c[2][8][4], uint32_t aB, uint32_t bB,
                                            int wm, int wn, int lane)
{
    const int i8  = lane & 7;
    const int sel = lane >> 3;
    const int arow_off = (sel & 1) * 8 + i8;
    const int akof     = (sel >> 1) * 8;
    const int bfsel    = sel >> 1;
    const int bkof     = (sel & 1) * 8;
    #pragma unroll
    for (int ks = 0; ks < 4; ks++) {
        unsigned a[2][4];
        #pragma unroll
        for (int mi = 0; mi < 2; mi++) {
            const int row = wm * 32 + mi * 16 + arow_off;
            ldsm4(a[mi], aB + (uint32_t)(row * 144 + (ks * 16 + akof) * 2));
        }
        #pragma unroll
        for (int j = 0; j < 4; j++) {
            unsigned bq[4];
            const int row = wn * 64 + (2 * j + bfsel) * 8 + i8;
            ldsm4(bq, bB + (uint32_t)(row * 144 + (ks * 16 + bkof) * 2));
            mma_h(c[0][2 * j],     a[0], bq);
            mma_h(c[1][2 * j],     a[1], bq);
            mma_h(c[0][2 * j + 1], a[0], bq + 2);
            mma_h(c[1][2 * j + 1], a[1], bq + 2);
        }
    }
}

// ---------------------------------------------------------------------------
// Kernel 1: fused QKV projection (r9 config). grid (64, 24), 256 thr, 2 CTA/SM.
// ---------------------------------------------------------------------------
__global__ __launch_bounds__(256, 2) void qkv_kernel(
    const float* __restrict__ bq, const float* __restrict__ bk, const float* __restrict__ bv)
{
    extern __shared__ char smc[];
    const int tid  = threadIdx.x;
    const int m0   = blockIdx.x * 128;
    const int p0   = blockIdx.y * 2;
    const int lane = tid & 31, wid = tid >> 5;
    const int wm   = wid >> 1, wn = wid & 1;
    const int g    = lane >> 2, t = lane & 3;
    const uint32_t smb = (uint32_t)__cvta_generic_to_shared(smc);

    // per-tile: A 1024 chunks of 16B, B 1024 chunks; 4 each per thread
    const __half* aS[4]; uint32_t aO[4];
    const __half* bS[4];
    #pragma unroll
    for (int i = 0; i < 4; i++) {
        int c = tid + i * 256;
        int row = c >> 3, cpos = c & 7;
        aS[i] = g_xh + (size_t)(m0 + row) * E_ + cpos * 8;
        aO[i] = (uint32_t)(row * 144 + cpos * 16);
        int p = p0 + (row >> 6), op = p >> 4, hh = p & 15, d = row & 63;
        const __half* base = (op == 0) ? g_Wqh : (op == 1) ? g_Wkh : g_Wvh;
        bS[i] = base + ((size_t)hh * D_ + d) * E_ + cpos * 8;
    }

    // prologue: tile 0 -> stage 0
    #pragma unroll
    for (int i = 0; i < 4; i++) {
        cp16(smb + A_STB(0) + aO[i], aS[i]);
        cp16(smb + B_STB(0) + aO[i], bS[i]);
    }
    cp_commit();

    float c[2][8][4];
    #pragma unroll
    for (int mi = 0; mi < 2; mi++)
        #pragma unroll
        for (int f = 0; f < 8; f++)
            #pragma unroll
            for (int r = 0; r < 4; r++) c[mi][f][r] = 0.f;

    for (int kt = 0; kt < 16; kt++) {
        cp_wait0();
        __syncthreads();
        if (kt + 1 < 16) {
            const uint32_t s = (uint32_t)((kt + 1) & 1);
            #pragma unroll
            for (int i = 0; i < 4; i++) {
                cp16(smb + A_STB(s) + aO[i], aS[i] + (size_t)(kt + 1) * 64);
                cp16(smb + B_STB(s) + aO[i], bS[i] + (size_t)(kt + 1) * 64);
            }
            cp_commit();
        }
        gemm_tile64(c, smb + A_STB(kt & 1), smb + B_STB(kt & 1), wm, wn, lane);
    }

    // epilogue: bias, scale Q (0.125*log2e), fp16-round, coalesced store
    const int p  = p0 + wn;
    const int op = p >> 4, hh = p & 15;
    const float* bb = ((op == 0) ? bq : (op == 1) ? bk : bv) + hh * D_;
    __half* outb = (op == 0) ? g_qh : (op == 1) ? g_kh : g_vh;
    const float scl = (op == 0) ? (0.125f * LOG2E) : 1.0f;

    #pragma unroll
    for (int mi = 0; mi < 2; mi++) {
        #pragma unroll
        for (int rr = 0; rr < 2; rr++) {
            const int gr = m0 + wm * 32 + mi * 16 + g + rr * 8;
            const int bbi = gr >> 11, ssi = gr & 2047;
            __half* ob = outb + (((size_t)bbi * H_ + hh) * S_ + ssi) * D_;
            #pragma unroll
            for (int f = 0; f < 8; f++) {
                const int col = f * 8 + t * 2;
                float v0 = (c[mi][f][rr * 2 + 0] + bb[col])     * scl;
                float v1 = (c[mi][f][rr * 2 + 1] + bb[col + 1]) * scl;
                *(unsigned*)(ob + col) = pack2h(v0, v1);
            }
        }
    }
}

// ---------------------------------------------------------------------------
// Kernel 3: output projection (r9 config). grid (64, 8), 256 thr, 2 CTA/SM.
// ---------------------------------------------------------------------------
__global__ __launch_bounds__(256, 2) void oproj_kernel(
    const float* __restrict__ bo, float* __restrict__ out)
{
    extern __shared__ char smc[];
    const int tid  = threadIdx.x;
    const int m0   = blockIdx.x * 128;
    const int n0   = blockIdx.y * 128;
    const int lane = tid & 31, wid = tid >> 5;
    const int wm   = wid >> 1, wn = wid & 1;
    const int g    = lane >> 2, t = lane & 3;
    const uint32_t smb = (uint32_t)__cvta_generic_to_shared(smc);

    const __half* aS[4]; uint32_t aO[4];
    const __half* bS[4];
    #pragma unroll
    for (int i = 0; i < 4; i++) {
        int c = tid + i * 256;
        int row = c >> 3, cpos = c & 7;
        aS[i] = g_ctxh + (size_t)(m0 + row) * E_ + cpos * 8;
        aO[i] = (uint32_t)(row * 144 + cpos * 16);
        bS[i] = g_Woh + (size_t)(n0 + row) * E_ + cpos * 8;
    }

    #pragma unroll
    for (int i = 0; i < 4; i++) {
        cp16(smb + A_STB(0) + aO[i], aS[i]);
        cp16(smb + B_STB(0) + aO[i], bS[i]);
    }
    cp_commit();

    float c[2][8][4];
    #pragma unroll
    for (int mi = 0; mi < 2; mi++)
        #pragma unroll
        for (int f = 0; f < 8; f++)
            #pragma unroll
            for (int r = 0; r < 4; r++) c[mi][f][r] = 0.f;

    for (int kt = 0; kt < 16; kt++) {
        cp_wait0();
        __syncthreads();
        if (kt + 1 < 16) {
            const uint32_t s = (uint32_t)((kt + 1) & 1);
            #pragma unroll
            for (int i = 0; i < 4; i++) {
                cp16(smb + A_STB(s) + aO[i], aS[i] + (size_t)(kt + 1) * 64);
                cp16(smb + B_STB(s) + aO[i], bS[i] + (size_t)(kt + 1) * 64);
            }
            cp_commit();
        }
        gemm_tile64(c, smb + A_STB(kt & 1), smb + B_STB(kt & 1), wm, wn, lane);
    }

    #pragma unroll
    for (int mi = 0; mi < 2; mi++) {
        const int r0 = m0 + wm * 32 + mi * 16 + g;
        #pragma unroll
        for (int f = 0; f < 8; f++) {
            const int col = n0 + wn * 64 + f * 8 + t * 2;
            const float b0v = bo[col], b1v = bo[col + 1];
            float2 v0; v0.x = c[mi][f][0] + b0v; v0.y = c[mi][f][1] + b1v;
            *(float2*)(out + (size_t)r0 * E_ + col) = v0;
            float2 v1; v1.x = c[mi][f][2] + b0v; v1.y = c[mi][f][3] + b1v;
            *(float2*)(out + (size_t)(r0 + 8) * E_ + col) = v1;
        }
    }
}

// ---------------------------------------------------------------------------
// Kernel 2: causal flash attention (r12-validated version, unchanged).
// 128 thr / 4 warps (warp = 32 q-rows), Bq=128, Bkv=64, 2 CTA/SM.
// smem rows 144B: Q[128]@0 | K 2x[64]@18432 | V 2x[64]@36864.
// ---------------------------------------------------------------------------
#define FLASH_SMEM 55296
#define FK_STB(s) (18432u + (uint32_t)(s) * 9216u)
#define FV_STB(s) (36864u + (uint32_t)(s) * 9216u)

__global__ __launch_bounds__(128, 2) void flash_kernel()
{
    extern __shared__ char smc[];
    const uint32_t smb = (uint32_t)__cvta_generic_to_shared(smc);

    const int iq = (int)(gridDim.x - 1 - blockIdx.x);   // heavy-first
    const int h = blockIdx.y, b = blockIdx.z;
    const int q0 = iq * 128;
    const size_t head = ((size_t)b * H_ + h) * S_ * D_;
    const __half* Qg = g_qh + head;
    const __half* Kg = g_kh + head;
    const __half* Vg = g_vh + head;

    const int tid  = threadIdx.x;
    const int lane = tid & 31, wid = tid >> 5;
    const int g    = lane >> 2, t = lane & 3;
    const int i8   = lane & 7, sel = lane >> 3;
    const int bfsel = sel >> 1;
    const int bkof  = (sel & 1) * 8;

    const int r0 = tid >> 3, cpos = tid & 7;
    const uint32_t sOff = (uint32_t)(r0 * 144 + cpos * 16);
    const __half* kBaseG = Kg + (size_t)r0 * D_ + cpos * 8;
    const ptrdiff_t v_delta = Vg - Kg;

    // prologue: Q (8 chunks/thread) + K/V tile 0 (4 chunks/thread each)
    #pragma unroll
    for (int i = 0; i < 8; i++)
        cp16(smb + sOff + (uint32_t)i * 2304u,
             Qg + (size_t)(q0 + r0 + i * 16) * D_ + cpos * 8);
    #pragma unroll
    for (int i = 0; i < 4; i++) {
        cp16(smb + FK_STB(0) + sOff + (uint32_t)i * 2304u, kBaseG + (size_t)i * 16 * D_);
        cp16(smb + FV_STB(0) + sOff + (uint32_t)i * 2304u, kBaseG + v_delta + (size_t)i * 16 * D_);
    }
    cp_commit();
    cp_wait0();
    __syncthreads();

    // Q fragments via ldmatrix (warp-private 32 rows, 2 m16-tiles)
    unsigned aQ[2][4][4];
    {
        const int kof = (sel >> 1) * 8;
        #pragma unroll
        for (int mi = 0; mi < 2; mi++) {
            const int row = wid * 32 + mi * 16 + (sel & 1) * 8 + i8;
            #pragma unroll
            for (int kk = 0; kk < 4; kk++)
                ldsm4(aQ[mi][kk], smb + (uint32_t)(row * 144 + (kk * 16 + kof) * 2));
        }
    }

    float cO[2][8][4];
    #pragma unroll
    for (int mi = 0; mi < 2; mi++)
        #pragma unroll
        for (int f = 0; f < 8; f++)
            #pragma unroll
            for (int r = 0; r < 4; r++) cO[mi][f][r] = 0.f;
    float mS[4] = {-1e30f, -1e30f, -1e30f, -1e30f};
    float lS[4] = {0.f, 0.f, 0.f, 0.f};

    const int jtmax = 2 * iq + 1;
    for (int jt = 0; jt <= jtmax; jt++) {
        if (jt > 0) {
            cp_wait0();
            __syncthreads();
        }
        if (jt < jtmax) {
            const uint32_t st = (uint32_t)((jt + 1) & 1);
            const size_t src = (size_t)(jt + 1) * 4096;
            #pragma unroll
            for (int i = 0; i < 4; i++) {
                cp16(smb + FK_STB(st) + sOff + (uint32_t)i * 2304u,
                     kBaseG + src + (size_t)i * 16 * D_);
                cp16(smb + FV_STB(st) + sOff + (uint32_t)i * 2304u,
                     kBaseG + v_delta + src + (size_t)i * 16 * D_);
            }
            cp_commit();
        }
        const uint32_t kBase = smb + FK_STB(jt & 1);
        const uint32_t vBase = smb + FV_STB(jt & 1);
        const int k0 = jt * 64;

        // S = Q K^T
        float cS[2][8][4];
        #pragma unroll
        for (int mi = 0; mi < 2; mi++)
            #pragma unroll
            for (int f = 0; f < 8; f++)
                #pragma unroll
                for (int r = 0; r < 4; r++) cS[mi][f][r] = 0.f;
        #pragma unroll
        for (int kk = 0; kk < 4; kk++) {
            #pragma unroll
            for (int j = 0; j < 4; j++) {
                unsigned bq[4];
                const int row = (2 * j + bfsel) * 8 + i8;
                ldsm4(bq, kBase + (uint32_t)(row * 144 + (kk * 16 + bkof) * 2));
                #pragma unroll
                for (int mi = 0; mi < 2; mi++) {
                    mma_h(cS[mi][2 * j],     aQ[mi][kk], bq);
                    mma_h(cS[mi][2 * j + 1], aQ[mi][kk], bq + 2);
                }
            }
        }

        // causal mask (diagonal-crossing tiles only)
        if (jt >= 2 * iq) {
            #pragma unroll
            for (int mi = 0; mi < 2; mi++) {
                const int ra = q0 + wid * 32 + mi * 16 + g, rb = ra + 8;
                #pragma unroll
                for (int f = 0; f < 8; f++) {
                    const int col = k0 + f * 8 + t * 2;
                    if (col     > ra) cS[mi][f][0] = -1e30f;
                    if (col + 1 > ra) cS[mi][f][1] = -1e30f;
                    if (col     > rb) cS[mi][f][2] = -1e30f;
                    if (col + 1 > rb) cS[mi][f][3] = -1e30f;
                }
            }
        }

        // online softmax (exp2 domain; Q pre-scaled by 0.125*log2e)
        #pragma unroll
        for (int mi = 0; mi < 2; mi++) {
            float rm0 = -1e30f, rm1 = -1e30f;
            #pragma unroll
            for (int f = 0; f < 8; f++) {
                rm0 = fmaxf(rm0, fmaxf(cS[mi][f][0], cS[mi][f][1]));
                rm1 = fmaxf(rm1, fmaxf(cS[mi][f][2], cS[mi][f][3]));
            }
            rm0 = fmaxf(rm0, __shfl_xor_sync(0xffffffffu, rm0, 1));
            rm0 = fmaxf(rm0, __shfl_xor_sync(0xffffffffu, rm0, 2));
            rm1 = fmaxf(rm1, __shfl_xor_sync(0xffffffffu, rm1, 1));
            rm1 = fmaxf(rm1, __shfl_xor_sync(0xffffffffu, rm1, 2));

            const float nm0 = fmaxf(mS[mi * 2],     rm0);
            const float nm1 = fmaxf(mS[mi * 2 + 1], rm1);
            const float corr0 = exp2f(mS[mi * 2]     - nm0);
            const float corr1 = exp2f(mS[mi * 2 + 1] - nm1);
            mS[mi * 2] = nm0; mS[mi * 2 + 1] = nm1;

            float rs0 = 0.f, rs1 = 0.f;
            #pragma unroll
            for (int f = 0; f < 8; f++) {
                cS[mi][f][0] = exp2f(cS[mi][f][0] - nm0);
                cS[mi][f][1] = exp2f(cS[mi][f][1] - nm0);
                cS[mi][f][2] = exp2f(cS[mi][f][2] - nm1);
                cS[mi][f][3] = exp2f(cS[mi][f][3] - nm1);
                rs0 += cS[mi][f][0] + cS[mi][f][1];
                rs1 += cS[mi][f][2] + cS[mi][f][3];
            }
            rs0 += __shfl_xor_sync(0xffffffffu, rs0, 1);
            rs0 += __shfl_xor_sync(0xffffffffu, rs0, 2);
            rs1 += __shfl_xor_sync(0xffffffffu, rs1, 1);
            rs1 += __shfl_xor_sync(0xffffffffu, rs1, 2);
            lS[mi * 2]     = lS[mi * 2]     * corr0 + rs0;
            lS[mi * 2 + 1] = lS[mi * 2 + 1] * corr1 + rs1;
            #pragma unroll
            for (int f = 0; f < 8; f++) {
                cO[mi][f][0] *= corr0; cO[mi][f][1] *= corr0;
                cO[mi][f][2] *= corr1; cO[mi][f][3] *= corr1;
            }
        }

        // O += P V : P packed from accumulators; V [key][d] via ldmatrix.trans
        #pragma unroll
        for (int kk = 0; kk < 4; kk++) {
            unsigned aP[2][4];
            #pragma unroll
            for (int mi = 0; mi < 2; mi++) {
                aP[mi][0] = pack2h(cS[mi][2 * kk][0],     cS[mi][2 * kk][1]);
                aP[mi][1] = pack2h(cS[mi][2 * kk][2],     cS[mi][2 * kk][3]);
                aP[mi][2] = pack2h(cS[mi][2 * kk + 1][0], cS[mi][2 * kk + 1][1]);
                aP[mi][3] = pack2h(cS[mi][2 * kk + 1][2], cS[mi][2 * kk + 1][3]);
            }
            #pragma unroll
            for (int j = 0; j < 4; j++) {
                unsigned bq[4];
                const int row = kk * 16 + (sel & 1) * 8 + i8;
                const int colb = (2 * j + (sel >> 1)) * 16;
                ldsm4t(bq, vBase + (uint32_t)(row * 144 + colb));
                #pragma unroll
                for (int mi = 0; mi < 2; mi++) {
                    mma_h(cO[mi][2 * j],     aP[mi], bq);
                    mma_h(cO[mi][2 * j + 1], aP[mi], bq + 2);
                }
            }
        }
    }

    // epilogue: normalize, fp16-round, write ctx [s][h*d]
    #pragma unroll
    for (int mi = 0; mi < 2; mi++) {
        const float inv0 = 1.0f / lS[mi * 2];
        const float inv1 = 1.0f / lS[mi * 2 + 1];
        const int q_a = q0 + wid * 32 + mi * 16 + g, q_b = q_a + 8;
        #pragma unroll
        for (int f = 0; f < 8; f++) {
            const int col = h * D_ + f * 8 + t * 2;
            *(unsigned*)(g_ctxh + ((size_t)b * S_ + q_a) * E_ + col) =
                pack2h(cO[mi][f][0] * inv0, cO[mi][f][1] * inv0);
            *(unsigned*)(g_ctxh + ((size_t)b * S_ + q_b) * E_ + col) =
                pack2h(cO[mi][f][2] * inv1, cO[mi][f][3] * inv1);
        }
    }
}

// ---------------------------------------------------------------------------
extern "C" void kernel_launch(void* const* d_in, const int* in_sizes, int n_in,
                              void* d_out, int out_size)
{
    const float* x  = (const float*)d_in[0];
    const float* Wq = (const float*)d_in[1];
    const float* Wk = (const float*)d_in[2];
    const float* Wv = (const float*)d_in[3];
    const float* bq = (const float*)d_in[4];
    const float* bk = (const float*)d_in[5];
    const float* bv = (const float*)d_in[6];
    const float* Wo = (const float*)d_in[7];
    const float* bo = (const float*)d_in[8];
    float* out = (float*)d_out;

    cudaFuncSetAttribute(qkv_kernel,   cudaFuncAttributeMaxDynamicSharedMemorySize, GEMM_SMEM);
    cudaFuncSetAttribute(flash_kernel, cudaFuncAttributeMaxDynamicSharedMemorySize, FLASH_SMEM);
    cudaFuncSetAttribute(oproj_kernel, cudaFuncAttributeMaxDynamicSharedMemorySize, GEMM_SMEM);

    prep_kernel<<<2368, 256>>>(x, Wq, Wk, Wv, Wo);
    qkv_kernel<<<dim3(BS_ / 128, 24), 256, GEMM_SMEM>>>(bq, bk, bv);
    flash_kernel<<<dim3(S_ / 128, H_, B_), 128, FLASH_SMEM>>>();
    oproj_kernel<<<dim3(BS_ / 128, E_ / 128), 256, GEMM_SMEM>>>(bo, out);
}